// round 3
// baseline (speedup 1.0000x reference)
#include <cuda_runtime.h>
#include <math.h>
#include <stdint.h>

// Problem constants
#define BATCH 8
#define LV    16384          // leaves per batch
#define NNODE 32767          // nodes per batch (2*LV-1)
#define DIN   256
#define DH    256
#define NC    1024           // packed output cols: 768 (iou) + 256 (f)
#define TOTAL_ROWS (BATCH * NNODE)   // 262136

// ---------------- scratch (device globals; no allocation allowed) -----------
__device__ float g_Wx[DIN * NC];                       // [W_iou | W_f]
__device__ float g_Uc[DH * NC];                        // [U_iou | U_f]
__device__ float g_xproj[(size_t)TOTAL_ROWS * NC];     // x @ [W_iou|W_f], all nodes
__device__ float g_h[(size_t)TOTAL_ROWS * DH];
__device__ float g_c[(size_t)TOTAL_ROWS * DH];
__device__ float g_R[(size_t)BATCH * LV * NC];         // recurrent proj of child level

__device__ __forceinline__ float sigm(float x) { return 1.0f / (1.0f + expf(-x)); }

// ---------------- weight packing --------------------------------------------
__global__ void pack_weights(const float* __restrict__ W_iou, const float* __restrict__ W_f,
                             const float* __restrict__ U_iou, const float* __restrict__ U_f) {
    int idx = blockIdx.x * blockDim.x + threadIdx.x;
    if (idx >= DIN * NC) return;
    int k = idx / NC, j = idx % NC;
    float wv, uv;
    if (j < 768) { wv = W_iou[k * 768 + j];        uv = U_iou[k * 768 + j]; }
    else         { wv = W_f[k * 256 + (j - 768)];  uv = U_f[k * 256 + (j - 768)]; }
    g_Wx[idx] = wv;
    g_Uc[idx] = uv;
}

// ---------------- GEMM: C[M x 1024] = A[M x 256] @ W[256 x 1024] ------------
// A row m -> Abase + ((m/rpb)*node_stride + row_off + (m%rpb)) * 256
//   xproj pass: Aext=x, asel=0, rpb=M, row_off=0, node_stride=0  (rows contiguous)
//   rec pass  : asel=1 (g_h), rpb=2n, row_off=2n-1, node_stride=NNODE
// wsel: 0 -> g_Wx, 1 -> g_Uc.   csel: 0 -> g_xproj, 1 -> g_R.
#define BM 64
#define BN 64
#define BK 16

__global__ __launch_bounds__(256) void gemm64(
    const float* __restrict__ Aext, int asel, int wsel, int csel,
    int M, int rpb, int row_off, int node_stride)
{
    __shared__ float As[BM][BK + 1];
    __shared__ float Bs[BK][BN + 1];

    const float* Abase = asel ? g_h : Aext;
    const float* W     = wsel ? g_Uc : g_Wx;
    float*       C     = csel ? g_R  : g_xproj;

    const int tid = threadIdx.x;          // 256 threads
    const int tx = tid & 15;
    const int ty = tid >> 4;
    const int row0 = blockIdx.y * BM;
    const int col0 = blockIdx.x * BN;

    // A tile load coords: one float4 per thread (64 rows x 16 cols)
    const int a_lr = tid >> 2;            // 0..63
    const int a_lc = (tid & 3) * 4;       // 0,4,8,12
    // B tile load coords: one float4 per thread (16 rows x 64 cols)
    const int b_lr = tid >> 4;            // 0..15
    const int b_lc = (tid & 15) * 4;      // 0..60

    const float* arow = nullptr;
    {
        int m = row0 + a_lr;
        if (m < M) {
            int bb  = m / rpb;
            int loc = m - bb * rpb;
            arow = Abase + ((size_t)bb * node_stride + (size_t)(row_off + loc)) * 256;
        }
    }

    float acc[4][4];
#pragma unroll
    for (int i = 0; i < 4; i++)
#pragma unroll
        for (int j = 0; j < 4; j++) acc[i][j] = 0.0f;

    for (int k0 = 0; k0 < 256; k0 += BK) {
        float4 av = make_float4(0.f, 0.f, 0.f, 0.f);
        if (arow) av = *(const float4*)(arow + k0 + a_lc);
        As[a_lr][a_lc + 0] = av.x;
        As[a_lr][a_lc + 1] = av.y;
        As[a_lr][a_lc + 2] = av.z;
        As[a_lr][a_lc + 3] = av.w;

        float4 bv = *(const float4*)(W + (size_t)(k0 + b_lr) * NC + col0 + b_lc);
        Bs[b_lr][b_lc + 0] = bv.x;
        Bs[b_lr][b_lc + 1] = bv.y;
        Bs[b_lr][b_lc + 2] = bv.z;
        Bs[b_lr][b_lc + 3] = bv.w;

        __syncthreads();

#pragma unroll
        for (int kk = 0; kk < BK; kk++) {
            float ar[4], br[4];
#pragma unroll
            for (int i = 0; i < 4; i++) ar[i] = As[ty * 4 + i][kk];
#pragma unroll
            for (int j = 0; j < 4; j++) br[j] = Bs[kk][tx * 4 + j];
#pragma unroll
            for (int i = 0; i < 4; i++)
#pragma unroll
                for (int j = 0; j < 4; j++) acc[i][j] = fmaf(ar[i], br[j], acc[i][j]);
        }
        __syncthreads();
    }

#pragma unroll
    for (int i = 0; i < 4; i++) {
        int r = row0 + ty * 4 + i;
        if (r < M) {
            float4 v = make_float4(acc[i][0], acc[i][1], acc[i][2], acc[i][3]);
            *(float4*)(C + (size_t)r * NC + col0 + tx * 4) = v;
        }
    }
}

// ---------------- leaf elementwise ------------------------------------------
__global__ void leaf_k(const float* __restrict__ b_iou) {
    size_t idx = (size_t)blockIdx.x * blockDim.x + threadIdx.x;
    const size_t total = (size_t)BATCH * LV * DH;
    if (idx >= total) return;
    int d = (int)(idx % DH);
    size_t nl = idx / DH;               // 0..B*LV-1
    int bb = (int)(nl / LV);
    int k  = (int)(nl % LV);
    size_t row = (size_t)bb * NNODE + (LV - 1) + k;
    const float* xp = g_xproj + row * NC;
    float i = xp[d]       + b_iou[d];
    float o = xp[256 + d] + b_iou[256 + d];
    float u = xp[512 + d] + b_iou[512 + d];
    float c = sigm(i) * tanhf(u);
    g_c[row * DH + d] = c;
    g_h[row * DH + d] = sigm(o) * tanhf(c);
}

// ---------------- internal-level combine ------------------------------------
__global__ void combine_k(const float* __restrict__ b_iou, const float* __restrict__ b_f, int n) {
    size_t idx = (size_t)blockIdx.x * blockDim.x + threadIdx.x;
    const size_t total = (size_t)BATCH * n * DH;
    if (idx >= total) return;
    int d = (int)(idx % DH);
    size_t nl = idx / DH;
    int bb = (int)(nl / n);
    int k  = (int)(nl % n);
    int j  = n - 1 + k;                         // node index in heap
    size_t row = (size_t)bb * NNODE + j;

    size_t r0 = ((size_t)bb * 2 * n + 2 * k) * NC;   // child0 row in g_R
    size_t r1 = r0 + NC;                             // child1 row

    const float* xp = g_xproj + row * NC;
    float i = xp[d]       + b_iou[d]       + g_R[r0 + d]       + g_R[r1 + d];
    float o = xp[256 + d] + b_iou[256 + d] + g_R[r0 + 256 + d] + g_R[r1 + 256 + d];
    float u = xp[512 + d] + b_iou[512 + d] + g_R[r0 + 512 + d] + g_R[r1 + 512 + d];
    float fx = xp[768 + d] + b_f[d];
    float f0 = sigm(fx + g_R[r0 + 768 + d]);
    float f1 = sigm(fx + g_R[r1 + 768 + d]);

    size_t c0 = ((size_t)bb * NNODE + 2 * j + 1) * DH + d;
    size_t c1 = ((size_t)bb * NNODE + 2 * j + 2) * DH + d;
    float c = sigm(i) * tanhf(u) + f0 * g_c[c0] + f1 * g_c[c1];
    g_c[row * DH + d] = c;
    g_h[row * DH + d] = sigm(o) * tanhf(c);
}

// ---------------- output: concat(h[:,0,:], c[:,0,:]) ------------------------
__global__ void out_k(float* __restrict__ out) {
    int idx = blockIdx.x * blockDim.x + threadIdx.x;
    if (idx >= BATCH * 2 * DH) return;
    int bb = idx / (2 * DH);
    int d  = idx % (2 * DH);
    size_t row = (size_t)bb * NNODE;            // root is node 0
    out[idx] = (d < DH) ? g_h[row * DH + d] : g_c[row * DH + (d - DH)];
}

// ---------------- launch ----------------------------------------------------
extern "C" void kernel_launch(void* const* d_in, const int* in_sizes, int n_in,
                              void* d_out, int out_size) {
    const float* x     = (const float*)d_in[0];
    const float* W_iou = (const float*)d_in[1];
    const float* b_iou = (const float*)d_in[2];
    const float* U_iou = (const float*)d_in[3];
    const float* W_f   = (const float*)d_in[4];
    const float* b_f   = (const float*)d_in[5];
    const float* U_f   = (const float*)d_in[6];
    float* out = (float*)d_out;

    // 1. pack weights
    pack_weights<<<(DIN * NC + 255) / 256, 256>>>(W_iou, W_f, U_iou, U_f);

    // 2. input projection for ALL nodes: xproj = X @ [W_iou|W_f]
    {
        int M = TOTAL_ROWS;
        dim3 grid(NC / BN, (M + BM - 1) / BM);
        gemm64<<<grid, 256>>>(x, /*asel=*/0, /*wsel=*/0, /*csel=*/0,
                              M, /*rpb=*/M, /*row_off=*/0, /*node_stride=*/0);
    }

    // 3. leaves
    {
        size_t total = (size_t)BATCH * LV * DH;
        leaf_k<<<(unsigned)((total + 255) / 256), 256>>>(b_iou);
    }

    // 4. levels, bottom-up
    for (int n = LV / 2; n >= 1; n >>= 1) {
        int rows = BATCH * 2 * n;   // all children of this level
        dim3 grid(NC / BN, (rows + BM - 1) / BM);
        gemm64<<<grid, 256>>>(nullptr, /*asel=*/1, /*wsel=*/1, /*csel=*/1,
                              rows, /*rpb=*/2 * n, /*row_off=*/2 * n - 1,
                              /*node_stride=*/NNODE);
        size_t total = (size_t)BATCH * n * DH;
        combine_k<<<(unsigned)((total + 255) / 256), 256>>>(b_iou, b_f, n);
    }

    // 5. output
    out_k<<<(BATCH * 2 * DH + 255) / 256, 256>>>(out);
}

// round 5
// speedup vs baseline: 2.5496x; 2.5496x over previous
#include <cuda_runtime.h>
#include <cuda_bf16.h>
#include <math.h>
#include <stdint.h>

// Problem constants
#define BATCH 8
#define LV    16384
#define NNODE 32767
#define DH    256
#define NC    1024            // packed cols: 768 (iou) + 256 (f)
#define TOTAL_ROWS (BATCH * NNODE)

// GEMM tiling
#define TBM 128
#define TBN 64
#define TBK 32
#define SLDA 40               // padded smem stride (elements) -> 80B rows, conflict-free ldmatrix
#define SLDB 40

// ---------------- scratch (device globals) ----------------------------------
__device__ __nv_bfloat16 g_Wh[NC * 256];   // [W_iou|W_f]^T hi, [out_col][k]
__device__ __nv_bfloat16 g_Wl[NC * 256];
__device__ __nv_bfloat16 g_Uh[NC * 256];   // [U_iou|U_f]^T hi
__device__ __nv_bfloat16 g_Ul[NC * 256];
__device__ float g_xproj[(size_t)TOTAL_ROWS * NC];
__device__ float g_h[(size_t)TOTAL_ROWS * DH];
__device__ float g_c[(size_t)TOTAL_ROWS * DH];
__device__ float g_R[(size_t)BATCH * LV * NC];

__device__ __forceinline__ float sigm(float x) { return 1.0f / (1.0f + expf(-x)); }

// ---------------- PTX helpers ------------------------------------------------
__device__ __forceinline__ void ldsm4(uint32_t& r0, uint32_t& r1, uint32_t& r2, uint32_t& r3, uint32_t addr) {
    asm volatile("ldmatrix.sync.aligned.m8n8.x4.shared.b16 {%0,%1,%2,%3},[%4];"
                 : "=r"(r0), "=r"(r1), "=r"(r2), "=r"(r3) : "r"(addr));
}
__device__ __forceinline__ void ldsm2(uint32_t& r0, uint32_t& r1, uint32_t addr) {
    asm volatile("ldmatrix.sync.aligned.m8n8.x2.shared.b16 {%0,%1},[%2];"
                 : "=r"(r0), "=r"(r1) : "r"(addr));
}
__device__ __forceinline__ void mma16816(float* c, const uint32_t* a, const uint32_t* b) {
    asm volatile("mma.sync.aligned.m16n8k16.row.col.f32.bf16.bf16.f32 "
                 "{%0,%1,%2,%3},{%4,%5,%6,%7},{%8,%9},{%0,%1,%2,%3};"
                 : "+f"(c[0]), "+f"(c[1]), "+f"(c[2]), "+f"(c[3])
                 : "r"(a[0]), "r"(a[1]), "r"(a[2]), "r"(a[3]), "r"(b[0]), "r"(b[1]));
}

// ---------------- weight packing: transpose + bf16 hi/lo split ---------------
__global__ void pack_weights(const float* __restrict__ W_iou, const float* __restrict__ W_f,
                             const float* __restrict__ U_iou, const float* __restrict__ U_f) {
    int idx = blockIdx.x * blockDim.x + threadIdx.x;
    if (idx >= NC * 256) return;
    int j = idx / 256;        // output col
    int k = idx % 256;        // k index
    float wv = (j < 768) ? W_iou[k * 768 + j] : W_f[k * 256 + (j - 768)];
    float uv = (j < 768) ? U_iou[k * 768 + j] : U_f[k * 256 + (j - 768)];
    __nv_bfloat16 wh = __float2bfloat16_rn(wv);
    g_Wh[idx] = wh;
    g_Wl[idx] = __float2bfloat16_rn(wv - __bfloat162float(wh));
    __nv_bfloat16 uh = __float2bfloat16_rn(uv);
    g_Uh[idx] = uh;
    g_Ul[idx] = __float2bfloat16_rn(uv - __bfloat162float(uh));
}

// ---------------- tensor-core GEMM: C[M x 1024] = A[M x 256] @ W ------------
// A row m -> Abase + ((m/rpb)*node_stride + row_off + (m%rpb)) * 256 (fp32, split on the fly)
// 3-term bf16 split product: hi*hi + hi*lo + lo*hi  (~fp32 precision)
__global__ __launch_bounds__(256, 2) void gemm_tc(
    const float* __restrict__ Aext, int asel, int wsel, int csel,
    int M, int rpb, int row_off, int node_stride)
{
    __shared__ __nv_bfloat16 sAh[TBM * SLDA];
    __shared__ __nv_bfloat16 sAl[TBM * SLDA];
    __shared__ __nv_bfloat16 sBh[TBN * SLDB];
    __shared__ __nv_bfloat16 sBl[TBN * SLDB];

    const float* Abase = asel ? g_h : Aext;
    const __nv_bfloat16* Bhg = wsel ? g_Uh : g_Wh;
    const __nv_bfloat16* Blg = wsel ? g_Ul : g_Wl;
    float* C = csel ? g_R : g_xproj;

    const int tid = threadIdx.x;
    const int warp = tid >> 5, lane = tid & 31;
    const int wm = warp >> 1, wn = warp & 1;        // warps: 4 (m) x 2 (n)
    const int row0 = blockIdx.y * TBM;
    const int col0 = blockIdx.x * TBN;

    // A loader: each thread loads 4 float4s (rows tid/8 + {0,32,64,96}, col group tid%8)
    const int c4 = tid & 7;
    const float* ap[4];
    int asr[4];
#pragma unroll
    for (int i = 0; i < 4; i++) {
        int r = (tid >> 3) + i * 32;
        asr[i] = r;
        int m = row0 + r;
        if (m < M) {
            int bb = m / rpb;
            int loc = m - bb * rpb;
            ap[i] = Abase + ((size_t)bb * node_stride + (size_t)(row_off + loc)) * 256 + c4 * 4;
        } else ap[i] = nullptr;
    }
    // B loader: thread -> n = tid/4, k-chunk (tid%4)*8 (8 bf16 = uint4)
    const int bn = tid >> 2;
    const int bkc = (tid & 3) * 8;
    const __nv_bfloat16* bhp = Bhg + (size_t)(col0 + bn) * 256 + bkc;
    const __nv_bfloat16* blp = Blg + (size_t)(col0 + bn) * 256 + bkc;

    float acc[2][4][4];
#pragma unroll
    for (int mt = 0; mt < 2; mt++)
#pragma unroll
        for (int nt = 0; nt < 4; nt++)
#pragma unroll
            for (int e = 0; e < 4; e++) acc[mt][nt][e] = 0.0f;

    for (int k0 = 0; k0 < 256; k0 += TBK) {
        // --- load + split A tile ---
#pragma unroll
        for (int i = 0; i < 4; i++) {
            float4 v = ap[i] ? *(const float4*)(ap[i] + k0) : make_float4(0.f, 0.f, 0.f, 0.f);
            __nv_bfloat16 h0 = __float2bfloat16_rn(v.x);
            __nv_bfloat16 h1 = __float2bfloat16_rn(v.y);
            __nv_bfloat16 h2 = __float2bfloat16_rn(v.z);
            __nv_bfloat16 h3 = __float2bfloat16_rn(v.w);
            __nv_bfloat16 l0 = __float2bfloat16_rn(v.x - __bfloat162float(h0));
            __nv_bfloat16 l1 = __float2bfloat16_rn(v.y - __bfloat162float(h1));
            __nv_bfloat16 l2 = __float2bfloat16_rn(v.z - __bfloat162float(h2));
            __nv_bfloat16 l3 = __float2bfloat16_rn(v.w - __bfloat162float(h3));
            __nv_bfloat162* dh = (__nv_bfloat162*)&sAh[asr[i] * SLDA + c4 * 4];
            dh[0] = __nv_bfloat162(h0, h1);
            dh[1] = __nv_bfloat162(h2, h3);
            __nv_bfloat162* dl = (__nv_bfloat162*)&sAl[asr[i] * SLDA + c4 * 4];
            dl[0] = __nv_bfloat162(l0, l1);
            dl[1] = __nv_bfloat162(l2, l3);
        }
        // --- load B tile (pre-split bf16) ---
        *(uint4*)(&sBh[bn * SLDB + bkc]) = *(const uint4*)(bhp + k0);
        *(uint4*)(&sBl[bn * SLDB + bkc]) = *(const uint4*)(blp + k0);

        __syncthreads();

#pragma unroll
        for (int ks = 0; ks < TBK; ks += 16) {
            uint32_t ah[2][4], al[2][4], bh[4][2], bl[4][2];
#pragma unroll
            for (int mt = 0; mt < 2; mt++) {
                int mr = wm * 32 + mt * 16 + (lane & 15);
                int mc = ks + (lane >> 4) * 8;
                uint32_t ad = (uint32_t)__cvta_generic_to_shared(&sAh[mr * SLDA + mc]);
                ldsm4(ah[mt][0], ah[mt][1], ah[mt][2], ah[mt][3], ad);
                ad = (uint32_t)__cvta_generic_to_shared(&sAl[mr * SLDA + mc]);
                ldsm4(al[mt][0], al[mt][1], al[mt][2], al[mt][3], ad);
            }
#pragma unroll
            for (int nt = 0; nt < 4; nt++) {
                int nr = wn * 32 + nt * 8 + (lane & 7);
                int ncl = ks + ((lane >> 3) & 1) * 8;
                uint32_t ad = (uint32_t)__cvta_generic_to_shared(&sBh[nr * SLDB + ncl]);
                ldsm2(bh[nt][0], bh[nt][1], ad);
                ad = (uint32_t)__cvta_generic_to_shared(&sBl[nr * SLDB + ncl]);
                ldsm2(bl[nt][0], bl[nt][1], ad);
            }
#pragma unroll
            for (int mt = 0; mt < 2; mt++)
#pragma unroll
                for (int nt = 0; nt < 4; nt++) {
                    mma16816(acc[mt][nt], ah[mt], bh[nt]);   // hi*hi
                    mma16816(acc[mt][nt], ah[mt], bl[nt]);   // hi*lo
                    mma16816(acc[mt][nt], al[mt], bh[nt]);   // lo*hi
                }
        }
        __syncthreads();
    }

    // --- epilogue ---
#pragma unroll
    for (int mt = 0; mt < 2; mt++) {
        int r_lo = row0 + wm * 32 + mt * 16 + (lane >> 2);
        int r_hi = r_lo + 8;
#pragma unroll
        for (int nt = 0; nt < 4; nt++) {
            int cc = col0 + wn * 32 + nt * 8 + 2 * (lane & 3);
            if (r_lo < M)
                *(float2*)(&C[(size_t)r_lo * NC + cc]) = make_float2(acc[mt][nt][0], acc[mt][nt][1]);
            if (r_hi < M)
                *(float2*)(&C[(size_t)r_hi * NC + cc]) = make_float2(acc[mt][nt][2], acc[mt][nt][3]);
        }
    }
}

// ---------------- leaf elementwise ------------------------------------------
__global__ void leaf_k(const float* __restrict__ b_iou) {
    size_t idx = (size_t)blockIdx.x * blockDim.x + threadIdx.x;
    const size_t total = (size_t)BATCH * LV * DH;
    if (idx >= total) return;
    int d = (int)(idx % DH);
    size_t nl = idx / DH;
    int bb = (int)(nl / LV);
    int k  = (int)(nl % LV);
    size_t row = (size_t)bb * NNODE + (LV - 1) + k;
    const float* xp = g_xproj + row * NC;
    float i = xp[d]       + b_iou[d];
    float o = xp[256 + d] + b_iou[256 + d];
    float u = xp[512 + d] + b_iou[512 + d];
    float c = sigm(i) * tanhf(u);
    g_c[row * DH + d] = c;
    g_h[row * DH + d] = sigm(o) * tanhf(c);
}

// ---------------- internal-level combine ------------------------------------
__global__ void combine_k(const float* __restrict__ b_iou, const float* __restrict__ b_f, int n) {
    size_t idx = (size_t)blockIdx.x * blockDim.x + threadIdx.x;
    const size_t total = (size_t)BATCH * n * DH;
    if (idx >= total) return;
    int d = (int)(idx % DH);
    size_t nl = idx / DH;
    int bb = (int)(nl / n);
    int k  = (int)(nl % n);
    int j  = n - 1 + k;
    size_t row = (size_t)bb * NNODE + j;

    size_t r0 = ((size_t)bb * 2 * n + 2 * k) * NC;
    size_t r1 = r0 + NC;

    const float* xp = g_xproj + row * NC;
    float i = xp[d]       + b_iou[d]       + g_R[r0 + d]       + g_R[r1 + d];
    float o = xp[256 + d] + b_iou[256 + d] + g_R[r0 + 256 + d] + g_R[r1 + 256 + d];
    float u = xp[512 + d] + b_iou[512 + d] + g_R[r0 + 512 + d] + g_R[r1 + 512 + d];
    float fx = xp[768 + d] + b_f[d];
    float f0 = sigm(fx + g_R[r0 + 768 + d]);
    float f1 = sigm(fx + g_R[r1 + 768 + d]);

    size_t c0 = ((size_t)bb * NNODE + 2 * j + 1) * DH + d;
    size_t c1 = ((size_t)bb * NNODE + 2 * j + 2) * DH + d;
    float c = sigm(i) * tanhf(u) + f0 * g_c[c0] + f1 * g_c[c1];
    g_c[row * DH + d] = c;
    g_h[row * DH + d] = sigm(o) * tanhf(c);
}

// ---------------- output ----------------------------------------------------
__global__ void out_k(float* __restrict__ out) {
    int idx = blockIdx.x * blockDim.x + threadIdx.x;
    if (idx >= BATCH * 2 * DH) return;
    int bb = idx / (2 * DH);
    int d  = idx % (2 * DH);
    size_t row = (size_t)bb * NNODE;
    out[idx] = (d < DH) ? g_h[row * DH + d] : g_c[row * DH + (d - DH)];
}

// ---------------- launch ----------------------------------------------------
extern "C" void kernel_launch(void* const* d_in, const int* in_sizes, int n_in,
                              void* d_out, int out_size) {
    const float* x     = (const float*)d_in[0];
    const float* W_iou = (const float*)d_in[1];
    const float* b_iou = (const float*)d_in[2];
    const float* U_iou = (const float*)d_in[3];
    const float* W_f   = (const float*)d_in[4];
    const float* b_f   = (const float*)d_in[5];
    const float* U_f   = (const float*)d_in[6];
    float* out = (float*)d_out;

    // 1. pack + split weights (transposed, bf16 hi/lo)
    pack_weights<<<(NC * 256 + 255) / 256, 256>>>(W_iou, W_f, U_iou, U_f);

    // 2. input projection for ALL nodes (tensor cores)
    {
        int M = TOTAL_ROWS;
        dim3 grid(NC / TBN, (M + TBM - 1) / TBM);
        gemm_tc<<<grid, 256>>>(x, /*asel=*/0, /*wsel=*/0, /*csel=*/0,
                               M, /*rpb=*/M, /*row_off=*/0, /*node_stride=*/0);
    }

    // 3. leaves
    {
        size_t total = (size_t)BATCH * LV * DH;
        leaf_k<<<(unsigned)((total + 255) / 256), 256>>>(b_iou);
    }

    // 4. levels, bottom-up
    for (int n = LV / 2; n >= 1; n >>= 1) {
        int rows = BATCH * 2 * n;
        dim3 grid(NC / TBN, (rows + TBM - 1) / TBM);
        gemm_tc<<<grid, 256>>>(nullptr, /*asel=*/1, /*wsel=*/1, /*csel=*/1,
                               rows, /*rpb=*/2 * n, /*row_off=*/2 * n - 1,
                               /*node_stride=*/NNODE);
        size_t total = (size_t)BATCH * n * DH;
        combine_k<<<(unsigned)((total + 255) / 256), 256>>>(b_iou, b_f, n);
    }

    // 5. output
    out_k<<<(BATCH * 2 * DH + 255) / 256, 256>>>(out);
}

// round 8
// speedup vs baseline: 2.7651x; 1.0846x over previous
#include <cuda_runtime.h>
#include <cuda_bf16.h>
#include <math.h>
#include <stdint.h>

// Problem constants
#define BATCH 8
#define LV    16384
#define NNODE 32767
#define DH    256
#define NC    1024            // packed cols: 768 (iou) + 256 (f)
#define TOTAL_ROWS (BATCH * NNODE)   // 262136

// GEMM tiling
#define TBM 128
#define TBN 128
#define NSTAGE 3
#define STG_BYTES 32768       // Ah(8K) Al(8K) Bh(8K) Bl(8K)
#define SMEM_DYN (NSTAGE * STG_BYTES)

// ---------------- scratch (device globals) ----------------------------------
__device__ __nv_bfloat16 g_Wh[NC * 256];   // [W_iou|W_f]^T hi  [out_col][k]
__device__ __nv_bfloat16 g_Wl[NC * 256];
__device__ __nv_bfloat16 g_Uh[NC * 256];
__device__ __nv_bfloat16 g_Ul[NC * 256];
__device__ __nv_bfloat16 g_xh[(size_t)TOTAL_ROWS * 256];
__device__ __nv_bfloat16 g_xl[(size_t)TOTAL_ROWS * 256];
__device__ __nv_bfloat16 g_hh[(size_t)TOTAL_ROWS * 256];
__device__ __nv_bfloat16 g_hl[(size_t)TOTAL_ROWS * 256];
__device__ float g_xproj[(size_t)TOTAL_ROWS * NC];
__device__ float g_c[(size_t)TOTAL_ROWS * DH];
__device__ float g_R[(size_t)BATCH * LV * NC];

__device__ __forceinline__ float sigm(float x) { return 1.0f / (1.0f + expf(-x)); }

// ---------------- PTX helpers ------------------------------------------------
__device__ __forceinline__ uint32_t smem_u32(const void* p) {
    uint32_t a;
    asm("{ .reg .u64 t; cvta.to.shared.u64 t, %1; cvt.u32.u64 %0, t; }" : "=r"(a) : "l"(p));
    return a;
}
__device__ __forceinline__ void ldsm4(uint32_t& r0, uint32_t& r1, uint32_t& r2, uint32_t& r3, uint32_t addr) {
    asm volatile("ldmatrix.sync.aligned.m8n8.x4.shared.b16 {%0,%1,%2,%3},[%4];"
                 : "=r"(r0), "=r"(r1), "=r"(r2), "=r"(r3) : "r"(addr));
}
__device__ __forceinline__ void mma16816(float* c, const uint32_t* a, uint32_t b0, uint32_t b1) {
    asm volatile("mma.sync.aligned.m16n8k16.row.col.f32.bf16.bf16.f32 "
                 "{%0,%1,%2,%3},{%4,%5,%6,%7},{%8,%9},{%0,%1,%2,%3};"
                 : "+f"(c[0]), "+f"(c[1]), "+f"(c[2]), "+f"(c[3])
                 : "r"(a[0]), "r"(a[1]), "r"(a[2]), "r"(a[3]), "r"(b0), "r"(b1));
}
__device__ __forceinline__ void cp16(uint32_t dst, const void* src, int srcsz) {
    asm volatile("cp.async.cg.shared.global [%0], [%1], 16, %2;" :: "r"(dst), "l"(src), "r"(srcsz) : "memory");
}
#define CP_COMMIT() asm volatile("cp.async.commit_group;" ::: "memory")
#define CP_WAIT(n)  asm volatile("cp.async.wait_group %0;" :: "n"(n) : "memory")

// chunk-swizzled smem offset inside one 128x32 bf16 matrix (64B rows, 4x16B chunks)
__device__ __forceinline__ uint32_t swz(int r, int c) {
    return (uint32_t)(r * 64 + ((c ^ ((r >> 1) & 3)) << 4));
}

// ---------------- weight packing: transpose + bf16 hi/lo split ---------------
__global__ void pack_weights(const float* __restrict__ W_iou, const float* __restrict__ W_f,
                             const float* __restrict__ U_iou, const float* __restrict__ U_f) {
    int idx = blockIdx.x * blockDim.x + threadIdx.x;
    if (idx >= NC * 256) return;
    int j = idx / 256, k = idx % 256;
    float wv = (j < 768) ? W_iou[k * 768 + j] : W_f[k * 256 + (j - 768)];
    float uv = (j < 768) ? U_iou[k * 768 + j] : U_f[k * 256 + (j - 768)];
    __nv_bfloat16 wh = __float2bfloat16_rn(wv);
    g_Wh[idx] = wh;
    g_Wl[idx] = __float2bfloat16_rn(wv - __bfloat162float(wh));
    __nv_bfloat16 uh = __float2bfloat16_rn(uv);
    g_Uh[idx] = uh;
    g_Ul[idx] = __float2bfloat16_rn(uv - __bfloat162float(uh));
}

// ---------------- x hi/lo split ---------------------------------------------
__global__ void split_x(const float* __restrict__ x) {
    size_t i = (size_t)blockIdx.x * blockDim.x + threadIdx.x;
    const size_t n4 = (size_t)TOTAL_ROWS * 256 / 4;
    if (i >= n4) return;
    float4 v = ((const float4*)x)[i];
    __nv_bfloat16 h0 = __float2bfloat16_rn(v.x), h1 = __float2bfloat16_rn(v.y);
    __nv_bfloat16 h2 = __float2bfloat16_rn(v.z), h3 = __float2bfloat16_rn(v.w);
    ((__nv_bfloat162*)g_xh)[2 * i]     = __nv_bfloat162(h0, h1);
    ((__nv_bfloat162*)g_xh)[2 * i + 1] = __nv_bfloat162(h2, h3);
    ((__nv_bfloat162*)g_xl)[2 * i] = __nv_bfloat162(
        __float2bfloat16_rn(v.x - __bfloat162float(h0)),
        __float2bfloat16_rn(v.y - __bfloat162float(h1)));
    ((__nv_bfloat162*)g_xl)[2 * i + 1] = __nv_bfloat162(
        __float2bfloat16_rn(v.z - __bfloat162float(h2)),
        __float2bfloat16_rn(v.w - __bfloat162float(h3)));
}

// ---------------- mma.sync GEMM: C[M x 1024] = A[M x 256] @ W ----------------
// CTA tile 128x128x32, warp tile 64x32 (8 warps 2x4), 3-term bf16 split.
// A row m -> ((m/rpb)*node_stride + row_off + (m%rpb)) * 256
__global__ __launch_bounds__(256, 1)
void gemm_mma(int asel, int wsel, int csel, int M, int rpb, int row_off, int node_stride)
{
    extern __shared__ char smem[];
    const uint32_t sb = smem_u32(smem);
    const int tid = threadIdx.x, wid = tid >> 5, lane = tid & 31;
    const int wm = wid >> 2, wn = wid & 3;
    const int row0 = blockIdx.y * TBM;
    const int col0 = blockIdx.x * TBN;

    const __nv_bfloat16* Ahg = asel ? g_hh : g_xh;
    const __nv_bfloat16* Alg = asel ? g_hl : g_xl;
    const __nv_bfloat16* Bhg = wsel ? g_Uh : g_Wh;
    const __nv_bfloat16* Blg = wsel ? g_Ul : g_Wl;
    float* C = csel ? g_R : g_xproj;

    // loader: thread t owns row lr = t>>1 (A row and B row), chunks c2, c2+1
    const int lr = tid >> 1;
    const int c2 = (tid & 1) * 2;
    size_t aoff; int asz;
    {
        int m = row0 + lr;
        if (m < M) {
            int bb = m / rpb, loc = m - bb * rpb;
            aoff = ((size_t)bb * node_stride + (size_t)(row_off + loc)) * 256;
            asz = 16;
        } else { aoff = 0; asz = 0; }
    }
    const size_t boff = (size_t)(col0 + lr) * 256;
    const uint32_t s0 = swz(lr, c2), s1 = swz(lr, c2 + 1);

#define LOAD_CHUNK(kc, st) do {                                               \
        uint32_t bs = sb + (uint32_t)(st) * STG_BYTES;                        \
        int kg = (kc) * 32;                                                   \
        cp16(bs + s0,          Ahg + aoff + kg + c2 * 8,       asz);          \
        cp16(bs + s1,          Ahg + aoff + kg + c2 * 8 + 8,   asz);          \
        cp16(bs + 8192 + s0,   Alg + aoff + kg + c2 * 8,       asz);          \
        cp16(bs + 8192 + s1,   Alg + aoff + kg + c2 * 8 + 8,   asz);          \
        cp16(bs + 16384 + s0,  Bhg + boff + kg + c2 * 8,       16);           \
        cp16(bs + 16384 + s1,  Bhg + boff + kg + c2 * 8 + 8,   16);           \
        cp16(bs + 24576 + s0,  Blg + boff + kg + c2 * 8,       16);           \
        cp16(bs + 24576 + s1,  Blg + boff + kg + c2 * 8 + 8,   16);           \
        CP_COMMIT();                                                          \
    } while (0)

    float acc[4][4][4];
#pragma unroll
    for (int mt = 0; mt < 4; mt++)
#pragma unroll
        for (int nt = 0; nt < 4; nt++)
#pragma unroll
            for (int e = 0; e < 4; e++) acc[mt][nt][e] = 0.0f;

#define COMPUTE_CHUNK(st) do {                                                \
        uint32_t cb = sb + (uint32_t)(st) * STG_BYTES;                        \
        _Pragma("unroll")                                                     \
        for (int ks = 0; ks < 2; ks++) {                                      \
            uint32_t ah[4][4], al[4][4];                                      \
            int cch = ks * 2 + (lane >> 4);                                   \
            _Pragma("unroll")                                                 \
            for (int mt = 0; mt < 4; mt++) {                                  \
                int mr = wm * 64 + mt * 16 + (lane & 15);                     \
                uint32_t ad = cb + swz(mr, cch);                              \
                ldsm4(ah[mt][0], ah[mt][1], ah[mt][2], ah[mt][3], ad);        \
                ldsm4(al[mt][0], al[mt][1], al[mt][2], al[mt][3], ad + 8192); \
            }                                                                 \
            _Pragma("unroll")                                                 \
            for (int nt2 = 0; nt2 < 2; nt2++) {                               \
                int nr = wn * 32 + nt2 * 16 + (lane & 15);                    \
                uint32_t bd = cb + 16384 + swz(nr, cch);                      \
                uint32_t bh[4], bl[4];                                        \
                ldsm4(bh[0], bh[1], bh[2], bh[3], bd);                        \
                ldsm4(bl[0], bl[1], bl[2], bl[3], bd + 8192);                 \
                _Pragma("unroll")                                             \
                for (int mt = 0; mt < 4; mt++) {                              \
                    mma16816(acc[mt][nt2 * 2],     ah[mt], bh[0], bh[2]);     \
                    mma16816(acc[mt][nt2 * 2],     ah[mt], bl[0], bl[2]);     \
                    mma16816(acc[mt][nt2 * 2],     al[mt], bh[0], bh[2]);     \
                    mma16816(acc[mt][nt2 * 2 + 1], ah[mt], bh[1], bh[3]);     \
                    mma16816(acc[mt][nt2 * 2 + 1], ah[mt], bl[1], bl[3]);     \
                    mma16816(acc[mt][nt2 * 2 + 1], al[mt], bh[1], bh[3]);     \
                }                                                             \
            }                                                                 \
        }                                                                     \
    } while (0)

    // prologue: stages 0,1,2 <- chunks 0,1,2
    LOAD_CHUNK(0, 0);
    LOAD_CHUNK(1, 1);
    LOAD_CHUNK(2, 2);

    int st_c = 0;
#pragma unroll 1
    for (int kc = 0; kc < 6; kc++) {
        CP_WAIT(2);
        __syncthreads();
        COMPUTE_CHUNK(st_c);
        if (kc < 5) {
            __syncthreads();
            LOAD_CHUNK(kc + 3, st_c);
        }
        st_c = (st_c == 2) ? 0 : st_c + 1;
    }
    CP_WAIT(1); __syncthreads();
    COMPUTE_CHUNK(st_c);
    st_c = (st_c == 2) ? 0 : st_c + 1;
    CP_WAIT(0); __syncthreads();
    COMPUTE_CHUNK(st_c);

    // epilogue
#pragma unroll
    for (int mt = 0; mt < 4; mt++) {
        int r_lo = row0 + wm * 64 + mt * 16 + (lane >> 2);
        int r_hi = r_lo + 8;
#pragma unroll
        for (int nt = 0; nt < 4; nt++) {
            int cc = col0 + wn * 32 + nt * 8 + 2 * (lane & 3);
            if (r_lo < M)
                *(float2*)(&C[(size_t)r_lo * NC + cc]) = make_float2(acc[mt][nt][0], acc[mt][nt][1]);
            if (r_hi < M)
                *(float2*)(&C[(size_t)r_hi * NC + cc]) = make_float2(acc[mt][nt][2], acc[mt][nt][3]);
        }
    }
#undef LOAD_CHUNK
#undef COMPUTE_CHUNK
}

// ---------------- leaf elementwise ------------------------------------------
__global__ void leaf_k(const float* __restrict__ b_iou) {
    size_t idx = (size_t)blockIdx.x * blockDim.x + threadIdx.x;
    const size_t total = (size_t)BATCH * LV * DH;
    if (idx >= total) return;
    int d = (int)(idx % DH);
    size_t nl = idx / DH;
    int bb = (int)(nl / LV), k = (int)(nl % LV);
    size_t row = (size_t)bb * NNODE + (LV - 1) + k;
    const float* xp = g_xproj + row * NC;
    float i = xp[d]       + b_iou[d];
    float o = xp[256 + d] + b_iou[256 + d];
    float u = xp[512 + d] + b_iou[512 + d];
    float c = sigm(i) * tanhf(u);
    float h = sigm(o) * tanhf(c);
    g_c[row * DH + d] = c;
    __nv_bfloat16 hh = __float2bfloat16_rn(h);
    g_hh[row * DH + d] = hh;
    g_hl[row * DH + d] = __float2bfloat16_rn(h - __bfloat162float(hh));
}

// ---------------- internal-level combine ------------------------------------
__global__ void combine_k(const float* __restrict__ b_iou, const float* __restrict__ b_f, int n) {
    size_t idx = (size_t)blockIdx.x * blockDim.x + threadIdx.x;
    const size_t total = (size_t)BATCH * n * DH;
    if (idx >= total) return;
    int d = (int)(idx % DH);
    size_t nl = idx / DH;
    int bb = (int)(nl / n), k = (int)(nl % n);
    int j = n - 1 + k;
    size_t row = (size_t)bb * NNODE + j;

    size_t r0 = ((size_t)bb * 2 * n + 2 * k) * NC;
    size_t r1 = r0 + NC;

    const float* xp = g_xproj + row * NC;
    float i = xp[d]       + b_iou[d]       + g_R[r0 + d]       + g_R[r1 + d];
    float o = xp[256 + d] + b_iou[256 + d] + g_R[r0 + 256 + d] + g_R[r1 + 256 + d];
    float u = xp[512 + d] + b_iou[512 + d] + g_R[r0 + 512 + d] + g_R[r1 + 512 + d];
    float fx = xp[768 + d] + b_f[d];
    float f0 = sigm(fx + g_R[r0 + 768 + d]);
    float f1 = sigm(fx + g_R[r1 + 768 + d]);

    size_t c0 = ((size_t)bb * NNODE + 2 * j + 1) * DH + d;
    size_t c1 = ((size_t)bb * NNODE + 2 * j + 2) * DH + d;
    float c = sigm(i) * tanhf(u) + f0 * g_c[c0] + f1 * g_c[c1];
    float h = sigm(o) * tanhf(c);
    g_c[row * DH + d] = c;
    __nv_bfloat16 hh = __float2bfloat16_rn(h);
    g_hh[row * DH + d] = hh;
    g_hl[row * DH + d] = __float2bfloat16_rn(h - __bfloat162float(hh));
}

// ---------------- output ----------------------------------------------------
__global__ void out_k(float* __restrict__ out) {
    int idx = blockIdx.x * blockDim.x + threadIdx.x;
    if (idx >= BATCH * 2 * DH) return;
    int bb = idx / (2 * DH);
    int d  = idx % (2 * DH);
    size_t row = (size_t)bb * NNODE;
    if (d < DH)
        out[idx] = __bfloat162float(g_hh[row * DH + d]) + __bfloat162float(g_hl[row * DH + d]);
    else
        out[idx] = g_c[row * DH + (d - DH)];
}

// ---------------- launch ----------------------------------------------------
extern "C" void kernel_launch(void* const* d_in, const int* in_sizes, int n_in,
                              void* d_out, int out_size) {
    const float* x     = (const float*)d_in[0];
    const float* W_iou = (const float*)d_in[1];
    const float* b_iou = (const float*)d_in[2];
    const float* U_iou = (const float*)d_in[3];
    const float* W_f   = (const float*)d_in[4];
    const float* b_f   = (const float*)d_in[5];
    const float* U_f   = (const float*)d_in[6];
    float* out = (float*)d_out;

    cudaFuncSetAttribute(gemm_mma, cudaFuncAttributeMaxDynamicSharedMemorySize, SMEM_DYN);

    pack_weights<<<(NC * 256 + 255) / 256, 256>>>(W_iou, W_f, U_iou, U_f);
    {
        size_t n4 = (size_t)TOTAL_ROWS * 256 / 4;
        split_x<<<(unsigned)((n4 + 255) / 256), 256>>>(x);
    }

    // input projection for ALL nodes
    {
        int M = TOTAL_ROWS;
        dim3 grid(NC / TBN, (M + TBM - 1) / TBM);
        gemm_mma<<<grid, 256, SMEM_DYN>>>(0, 0, 0, M, M, 0, 0);
    }

    {
        size_t total = (size_t)BATCH * LV * DH;
        leaf_k<<<(unsigned)((total + 255) / 256), 256>>>(b_iou);
    }

    for (int n = LV / 2; n >= 1; n >>= 1) {
        int rows = BATCH * 2 * n;
        dim3 grid(NC / TBN, (rows + TBM - 1) / TBM);
        gemm_mma<<<grid, 256, SMEM_DYN>>>(1, 1, 1, rows, 2 * n, 2 * n - 1, NNODE);
        size_t total = (size_t)BATCH * n * DH;
        combine_k<<<(unsigned)((total + 255) / 256), 256>>>(b_iou, b_f, n);
    }

    out_k<<<(BATCH * 2 * DH + 255) / 256, 256>>>(out);
}